// round 4
// baseline (speedup 1.0000x reference)
#include <cuda_runtime.h>
#include <math.h>

// Problem constants (shapes are fixed by the dataset; guards handle generality)
#define NUM_CLASSES 10
#define MAXB   1024
#define MAXNE  50048
#define DD     64
#define GAMMA  1.0f
#define EPS    1e-12f

// Scratch (no cudaMalloc allowed) — re-initialized every kernel_launch call so
// graph replays are deterministic.
__device__ float g_class[MAXB * NUM_CLASSES];
__device__ float g_e2[MAXNE];
__device__ float g_x2[MAXB];
__device__ float g_beta;

// ---------------------------------------------------------------------------
// Prep: row norms for x and exemplars, beta = softplus(beta_raw), zero accum.
// ---------------------------------------------------------------------------
__global__ void prep_kernel(const float* __restrict__ x,
                            const float* __restrict__ ex,
                            const float* __restrict__ beta_raw,
                            int B, int NE) {
    int i = blockIdx.x * blockDim.x + threadIdx.x;
    if (i < NE) {
        const float4* p = (const float4*)(ex + (size_t)i * DD);
        float s = 0.f;
        #pragma unroll
        for (int j = 0; j < DD / 4; j++) {
            float4 v = p[j];
            s += v.x * v.x + v.y * v.y + v.z * v.z + v.w * v.w;
        }
        g_e2[i] = s;
    }
    if (i < B) {
        const float4* p = (const float4*)(x + (size_t)i * DD);
        float s = 0.f;
        #pragma unroll
        for (int j = 0; j < DD / 4; j++) {
            float4 v = p[j];
            s += v.x * v.x + v.y * v.y + v.z * v.z + v.w * v.w;
        }
        g_x2[i] = s;
    }
    if (i < B * NUM_CLASSES) g_class[i] = 0.f;
    if (i == 0) {
        float br = beta_raw[0];
        // softplus, numerically stable
        g_beta = (br > 20.f) ? br : log1pf(expf(br));
    }
}

// ---------------------------------------------------------------------------
// Main: tiled fp32 GEMM computing dot(x_b, e_n); epilogue forms
// d2 = x2 + e2 - 2*dot, gates exp on beta*d2 < 60 (skipped mass < 5e-16
// which is < 1e-3 * EPS relative to class_sims + EPS), and scatter-adds into
// per-(row,class) accumulators.
// ---------------------------------------------------------------------------
#define BM 64
#define BN 64
#define PAD 68   // row stride in floats: 16B-aligned, kills LDS bank conflicts

__global__ __launch_bounds__(256) void exemplar_kernel(
    const float* __restrict__ x, const float* __restrict__ ex,
    const int* __restrict__ labels, int B, int NE) {

    __shared__ float xs[BM][PAD];
    __shared__ float es[BN][PAD];
    __shared__ float e2s[BN];
    __shared__ float x2s[BM];
    __shared__ int   labs[BN];

    const int bm = blockIdx.y * BM;
    const int bn = blockIdx.x * BN;
    const int t = threadIdx.x;

    // Load x tile (64 rows x 64 floats) via float4
    for (int i = t; i < BM * (DD / 4); i += 256) {
        int r = i >> 4, c4 = i & 15;
        int row = bm + r;
        float4 v = (row < B) ? ((const float4*)(x + (size_t)row * DD))[c4]
                             : make_float4(0.f, 0.f, 0.f, 0.f);
        *(float4*)&xs[r][c4 * 4] = v;
    }
    // Load exemplar tile
    for (int i = t; i < BN * (DD / 4); i += 256) {
        int r = i >> 4, c4 = i & 15;
        int col = bn + r;
        float4 v = (col < NE) ? ((const float4*)(ex + (size_t)col * DD))[c4]
                              : make_float4(0.f, 0.f, 0.f, 0.f);
        *(float4*)&es[r][c4 * 4] = v;
    }
    if (t < BN) {
        int col = bn + t;
        e2s[t]  = (col < NE) ? g_e2[col] : 3.0e8f;  // huge -> always gated off
        labs[t] = (col < NE) ? labels[col] : 0;
    }
    if (t < BM) {
        int row = bm + t;
        x2s[t] = (row < B) ? g_x2[row] : 0.f;
    }
    __syncthreads();

    const int tx = t & 15, ty = t >> 4;
    const int r0 = ty * 4;

    float acc[4][4];
    #pragma unroll
    for (int i = 0; i < 4; i++)
        #pragma unroll
        for (int j = 0; j < 4; j++) acc[i][j] = 0.f;

    // k-vectorized inner loop: float4 LDS over k, 64 FFMA per 4-k step.
    // Column mapping col = tx + 16*j keeps b-loads low-conflict.
    #pragma unroll
    for (int k = 0; k < DD; k += 4) {
        float4 a[4], b[4];
        #pragma unroll
        for (int i = 0; i < 4; i++) a[i] = *(const float4*)&xs[r0 + i][k];
        #pragma unroll
        for (int j = 0; j < 4; j++) b[j] = *(const float4*)&es[tx + 16 * j][k];
        #pragma unroll
        for (int i = 0; i < 4; i++)
            #pragma unroll
            for (int j = 0; j < 4; j++)
                acc[i][j] += a[i].x * b[j].x + a[i].y * b[j].y +
                             a[i].z * b[j].z + a[i].w * b[j].w;
    }

    const float beta = g_beta;
    #pragma unroll
    for (int i = 0; i < 4; i++) {
        int row = bm + r0 + i;
        if (row >= B) continue;
        float x2 = x2s[r0 + i];
        #pragma unroll
        for (int j = 0; j < 4; j++) {
            int cl = tx + 16 * j;
            int col = bn + cl;
            if (col >= NE) continue;
            float d2 = x2 + e2s[cl] - 2.f * acc[i][j];
            d2 = fmaxf(d2, 0.f);
            float bd = beta * d2;
            if (bd < 60.f) {   // exp(-60)*NE ~ 4e-22 << 1e-3*EPS: safe to skip rest
                atomicAdd(&g_class[row * NUM_CLASSES + labs[cl]], expf(-bd));
            }
        }
    }
}

// ---------------------------------------------------------------------------
// Finalize: logits = GAMMA * log(class_sims + EPS)
// ---------------------------------------------------------------------------
__global__ void finalize_kernel(float* __restrict__ out, int n) {
    int i = blockIdx.x * blockDim.x + threadIdx.x;
    if (i < n) out[i] = GAMMA * logf(g_class[i] + EPS);
}

extern "C" void kernel_launch(void* const* d_in, const int* in_sizes, int n_in,
                              void* d_out, int out_size) {
    const float* x        = (const float*)d_in[0];
    const float* ex       = (const float*)d_in[1];
    const int*   labels   = (const int*)d_in[2];
    const float* beta_raw = (const float*)d_in[3];
    float* out = (float*)d_out;

    const int B  = in_sizes[0] / DD;
    const int NE = in_sizes[1] / DD;

    int prepN = NE > B * NUM_CLASSES ? NE : B * NUM_CLASSES;
    prep_kernel<<<(prepN + 255) / 256, 256>>>(x, ex, beta_raw, B, NE);

    dim3 grid((NE + BN - 1) / BN, (B + BM - 1) / BM);
    exemplar_kernel<<<grid, 256>>>(x, ex, labels, B, NE);

    finalize_kernel<<<(out_size + 255) / 256, 256>>>(out, out_size);
}

// round 6
// speedup vs baseline: 1.6382x; 1.6382x over previous
#include <cuda_runtime.h>
#include <cuda_bf16.h>
#include <stdint.h>
#include <math.h>

// ---------------------------------------------------------------------------
// Problem constants
// ---------------------------------------------------------------------------
#define NUM_CLASSES 10
#define DD     64
#define MAXB   1024
#define NE_PAD 50048           // 391 tiles of 128
#define GAMMA  1.0f
#define EPS    1e-12f

// Tiling (mma.sync path — tcgen05 is 'a'-gated and the harness emits compute_103)
#define TM 128
#define TN 128
#define GCOLS 37               // col-tile groups; grid = 8 x 37 = 296 = 2/SM
#define ROWB 144               // smem row stride in bytes (64 bf16 + 8 pad)

// ---------------------------------------------------------------------------
// Scratch (__device__ globals; no cudaMalloc allowed)
// ---------------------------------------------------------------------------
__device__ __nv_bfloat16 g_ebf[(size_t)NE_PAD * DD];
__device__ __nv_bfloat16 g_xbf[(size_t)MAXB * DD];
__device__ float g_e2[NE_PAD];
__device__ float g_x2[MAXB];
__device__ float g_class[MAXB * NUM_CLASSES];
__device__ float g_beta;

// ---------------------------------------------------------------------------
// PTX helpers (baseline ISA only: ldmatrix + mma.sync, no 'a' features)
// ---------------------------------------------------------------------------
__device__ __forceinline__ uint32_t smem_to_u32(const void* p) {
    uint32_t a;
    asm("{ .reg .u64 t; cvta.to.shared.u64 t, %1; cvt.u32.u64 %0, t; }"
        : "=r"(a) : "l"(p));
    return a;
}

__device__ __forceinline__ void ldsm_x4(uint32_t* r, uint32_t addr) {
    asm volatile("ldmatrix.sync.aligned.m8n8.x4.shared.b16 {%0,%1,%2,%3}, [%4];"
                 : "=r"(r[0]), "=r"(r[1]), "=r"(r[2]), "=r"(r[3]) : "r"(addr));
}
__device__ __forceinline__ void ldsm_x2(uint32_t* r, uint32_t addr) {
    asm volatile("ldmatrix.sync.aligned.m8n8.x2.shared.b16 {%0,%1}, [%2];"
                 : "=r"(r[0]), "=r"(r[1]) : "r"(addr));
}
__device__ __forceinline__ void mma_bf16(float* c, const uint32_t* a,
                                         const uint32_t* b) {
    asm volatile(
        "mma.sync.aligned.m16n8k16.row.col.f32.bf16.bf16.f32 "
        "{%0,%1,%2,%3}, {%4,%5,%6,%7}, {%8,%9}, {%0,%1,%2,%3};"
        : "+f"(c[0]), "+f"(c[1]), "+f"(c[2]), "+f"(c[3])
        : "r"(a[0]), "r"(a[1]), "r"(a[2]), "r"(a[3]), "r"(b[0]), "r"(b[1]));
}

// ---------------------------------------------------------------------------
// Prep: norms, bf16 conversion (padded), beta = softplus(beta_raw), zero bins.
// 4 threads per row (16 floats each); grid = (NE_PAD + MAXB)/64 blocks of 256.
// ---------------------------------------------------------------------------
__global__ void prep_kernel(const float* __restrict__ x,
                            const float* __restrict__ ex,
                            const float* __restrict__ beta_raw,
                            int B, int NE) {
    const int t = threadIdx.x;
    const int gid = blockIdx.x * 256 + t;
    if (gid < MAXB * NUM_CLASSES) g_class[gid] = 0.f;
    if (gid == 0) {
        float br = beta_raw[0];
        g_beta = (br > 20.f) ? br : log1pf(expf(br));
    }
    const int R = blockIdx.x * 64 + (t >> 2);   // padded row index
    const int part = t & 3;                      // 16-float segment
    bool is_x = false;
    int outr = R;
    const float* src = nullptr;
    if (R < NE_PAD) {
        if (R < NE) src = ex + (size_t)R * DD + part * 16;
    } else {
        int xr = R - NE_PAD;
        if (xr >= MAXB) return;
        is_x = true; outr = xr;
        if (xr < B) src = x + (size_t)xr * DD + part * 16;
    }
    float v[16];
    float s = 0.f;
    if (src) {
        #pragma unroll
        for (int q = 0; q < 4; q++) {
            float4 f = ((const float4*)src)[q];
            v[4*q+0] = f.x; v[4*q+1] = f.y; v[4*q+2] = f.z; v[4*q+3] = f.w;
            s += f.x*f.x + f.y*f.y + f.z*f.z + f.w*f.w;
        }
    } else {
        #pragma unroll
        for (int q = 0; q < 16; q++) v[q] = 0.f;
    }
    s += __shfl_xor_sync(0xFFFFFFFFu, s, 1);
    s += __shfl_xor_sync(0xFFFFFFFFu, s, 2);
    alignas(16) __nv_bfloat16 hb[16];
    #pragma unroll
    for (int q = 0; q < 16; q++) hb[q] = __float2bfloat16(v[q]);
    __nv_bfloat16* dst =
        (is_x ? (g_xbf + (size_t)outr * DD) : (g_ebf + (size_t)outr * DD)) + part * 16;
    ((uint4*)dst)[0] = ((uint4*)hb)[0];
    ((uint4*)dst)[1] = ((uint4*)hb)[1];
    if (part == 0) {
        if (is_x) g_x2[outr] = (outr < B) ? s : 0.f;
        else      g_e2[outr] = (outr < NE) ? s : 3.0e8f;  // padding: gate never fires
    }
}

// ---------------------------------------------------------------------------
// Main: HMMA (mma.sync bf16) 128x128x64 tiles + gated epilogue.
// Warp grid 2(M) x 4(N); warp tile 64x32; acc = 64 fp32 regs/thread.
// d2 from the bf16 GEMM is a FILTER only: survivors (beta*(d2-4) < 60) are
// recomputed exactly in fp32 from global memory before exp + atomic.
// ---------------------------------------------------------------------------
__global__ void __launch_bounds__(256, 1)
exemplar_mma_kernel(const float* __restrict__ x, const float* __restrict__ ex,
                    const int* __restrict__ labels, int B, int NE) {
    __shared__ __align__(16) char sA[TM * ROWB];
    __shared__ __align__(16) char sB[TN * ROWB];
    __shared__ float e2s[TN];
    __shared__ int   labs[TN];

    const int t = threadIdx.x;
    const int wid = t >> 5, lane = t & 31;
    const int warpM = wid >> 2;            // 0..1
    const int warpN = wid & 3;             // 0..3
    const int bm = blockIdx.y * TM;
    const int NT = (NE + TN - 1) / TN;

    const uint32_t saU = smem_to_u32(sA);
    const uint32_t sbU = smem_to_u32(sB);

    // Load A tile (128 rows x 64 bf16) once — padded linear layout.
    for (int i = t; i < TM * 8; i += 256) {
        int r = i >> 3, c = i & 7;
        *(uint4*)(sA + r * ROWB + c * 16) =
            *(const uint4*)(g_xbf + (size_t)(bm + r) * DD + c * 8);
    }

    // ldmatrix lane-address components
    const int rowA = (lane & 7) + ((lane >> 3) & 1) * 8;   // x4: row within m16
    const int kA   = ((lane >> 4) & 1) * 8;                // x4: k half
    const int l16  = lane & 15;
    const int rowBf = l16 & 7;                              // x2: n row
    const int kB    = ((l16 >> 3) & 1) * 8;                 // x2: k half

    // Per-thread x2 values for the 8 M-rows this thread's accs touch.
    const float beta = g_beta;
    float x2a[4], x2b[4];
    #pragma unroll
    for (int mi = 0; mi < 4; mi++) {
        int r0 = bm + warpM * 64 + mi * 16 + (lane >> 2);
        x2a[mi] = g_x2[r0];
        x2b[mi] = g_x2[r0 + 8];
    }

    for (int et = blockIdx.x; et < NT; et += GCOLS) {
        const int bn = et * TN;
        __syncthreads();   // previous epilogue done with labs/e2s/sB
        // Load B tile (128 exemplar rows x 64 bf16) + metadata.
        for (int i = t; i < TN * 8; i += 256) {
            int r = i >> 3, c = i & 7;
            *(uint4*)(sB + r * ROWB + c * 16) =
                *(const uint4*)(g_ebf + (size_t)(bn + r) * DD + c * 8);
        }
        for (int i = t; i < TN; i += 256) {
            int col = bn + i;
            e2s[i]  = g_e2[col];
            labs[i] = (col < NE) ? labels[col] : 0;
        }
        __syncthreads();

        // Per-thread e2 pairs for the 8 N-cols this thread's accs touch.
        float e2r[4][2];
        #pragma unroll
        for (int ni = 0; ni < 4; ni++) {
            int c0 = warpN * 32 + ni * 8 + 2 * (lane & 3);
            e2r[ni][0] = e2s[c0];
            e2r[ni][1] = e2s[c0 + 1];
        }

        float acc[4][4][4];
        #pragma unroll
        for (int mi = 0; mi < 4; mi++)
            #pragma unroll
            for (int ni = 0; ni < 4; ni++)
                #pragma unroll
                for (int r = 0; r < 4; r++) acc[mi][ni][r] = 0.f;

        #pragma unroll
        for (int ks = 0; ks < 4; ks++) {
            const int k0b = ks * 32;   // k offset in bytes (16 bf16)
            uint32_t af[4][4];
            #pragma unroll
            for (int mi = 0; mi < 4; mi++)
                ldsm_x4(af[mi], saU + (uint32_t)(warpM * 64 + mi * 16 + rowA) * ROWB
                                  + kA * 2 + k0b);
            uint32_t bf[4][2];
            #pragma unroll
            for (int ni = 0; ni < 4; ni++)
                ldsm_x2(bf[ni], sbU + (uint32_t)(warpN * 32 + ni * 8 + rowBf) * ROWB
                                  + kB * 2 + k0b);
            #pragma unroll
            for (int mi = 0; mi < 4; mi++)
                #pragma unroll
                for (int ni = 0; ni < 4; ni++)
                    mma_bf16(acc[mi][ni], af[mi], bf[ni]);
        }

        // Epilogue: gate on approximate d2; recompute survivors exactly.
        #pragma unroll
        for (int mi = 0; mi < 4; mi++) {
            #pragma unroll
            for (int ni = 0; ni < 4; ni++) {
                #pragma unroll
                for (int r = 0; r < 4; r++) {
                    float x2v = (r >= 2) ? x2b[mi] : x2a[mi];
                    float e2v = e2r[ni][r & 1];
                    float d2a = x2v + e2v - 2.f * acc[mi][ni][r];
                    // margin 4 >> worst-case bf16 dot error (~0.7)
                    if (beta * (d2a - 4.f) < 60.f) {
                        int grow = bm + warpM * 64 + mi * 16 + (lane >> 2)
                                   + ((r >= 2) ? 8 : 0);
                        int cl = warpN * 32 + ni * 8 + 2 * (lane & 3) + (r & 1);
                        int col = bn + cl;
                        if (grow < B && col < NE) {
                            const float* xr = x  + (size_t)grow * DD;
                            const float* er = ex + (size_t)col  * DD;
                            float s = 0.f;
                            #pragma unroll
                            for (int q = 0; q < DD / 4; q++) {
                                float4 a = ((const float4*)xr)[q];
                                float4 e = ((const float4*)er)[q];
                                s += a.x*e.x + a.y*e.y + a.z*e.z + a.w*e.w;
                            }
                            float d2e = fmaxf(x2v + e2v - 2.f * s, 0.f);
                            float bd = beta * d2e;
                            // skipped mass <= NE*exp(-60) << 1e-3 * EPS
                            if (bd < 60.f)
                                atomicAdd(&g_class[grow * NUM_CLASSES + labs[cl]],
                                          expf(-bd));
                        }
                    }
                }
            }
        }
    }
}

// ---------------------------------------------------------------------------
// Finalize: logits = GAMMA * log(class_sims + EPS)
// ---------------------------------------------------------------------------
__global__ void finalize_kernel(float* __restrict__ out, int n) {
    int i = blockIdx.x * blockDim.x + threadIdx.x;
    if (i < n) out[i] = GAMMA * logf(g_class[i] + EPS);
}

// ---------------------------------------------------------------------------
extern "C" void kernel_launch(void* const* d_in, const int* in_sizes, int n_in,
                              void* d_out, int out_size) {
    const float* x        = (const float*)d_in[0];
    const float* ex       = (const float*)d_in[1];
    const int*   labels   = (const int*)d_in[2];
    const float* beta_raw = (const float*)d_in[3];
    float* out = (float*)d_out;

    const int B  = in_sizes[0] / DD;
    const int NE = in_sizes[1] / DD;

    const int prep_blocks = (NE_PAD + MAXB) / 64;   // 798
    prep_kernel<<<prep_blocks, 256>>>(x, ex, beta_raw, B, NE);

    dim3 grid(GCOLS, (B + TM - 1) / TM);            // 37 x 8
    exemplar_mma_kernel<<<grid, 256>>>(x, ex, labels, B, NE);

    finalize_kernel<<<(out_size + 255) / 256, 256>>>(out, out_size);
}

// round 7
// speedup vs baseline: 6.2379x; 3.8079x over previous
#include <cuda_runtime.h>
#include <cuda_bf16.h>
#include <stdint.h>
#include <math.h>

// ---------------------------------------------------------------------------
// Problem constants
// ---------------------------------------------------------------------------
#define NUM_CLASSES 10
#define DD     64
#define MAXB   1024
#define NE_PAD 50048           // 391 tiles of 128
#define GAMMA  1.0f
#define EPS    1e-12f

// Tiling (mma.sync path — tcgen05 is 'a'-gated; harness emits compute_103)
#define TM 128
#define TN 128
#define GCOLS 37               // grid = 8 x 37 = 296 CTAs = 2/SM, one wave
#define ROWB 144               // smem row stride in bytes (64 bf16 + 8 pad)

// Survivor queue
#define QCAP 2048
#define MAXSURV (4u * 1024u * 1024u)

// ---------------------------------------------------------------------------
// Scratch (__device__ globals; no cudaMalloc allowed)
// ---------------------------------------------------------------------------
__device__ __nv_bfloat16 g_ebf[(size_t)NE_PAD * DD];
__device__ __nv_bfloat16 g_xbf[(size_t)MAXB * DD];
__device__ float g_e2[NE_PAD];
__device__ float g_x2[MAXB];
__device__ float g_class[MAXB * NUM_CLASSES];
__device__ float g_beta;
__device__ unsigned int g_nsurv;
__device__ unsigned int g_surv[MAXSURV];

// ---------------------------------------------------------------------------
// PTX helpers (baseline ISA only: ldmatrix + mma.sync, no 'a' features)
// ---------------------------------------------------------------------------
__device__ __forceinline__ uint32_t smem_to_u32(const void* p) {
    uint32_t a;
    asm("{ .reg .u64 t; cvta.to.shared.u64 t, %1; cvt.u32.u64 %0, t; }"
        : "=r"(a) : "l"(p));
    return a;
}

__device__ __forceinline__ void ldsm_x4(uint32_t* r, uint32_t addr) {
    asm volatile("ldmatrix.sync.aligned.m8n8.x4.shared.b16 {%0,%1,%2,%3}, [%4];"
                 : "=r"(r[0]), "=r"(r[1]), "=r"(r[2]), "=r"(r[3]) : "r"(addr));
}
__device__ __forceinline__ void ldsm_x2(uint32_t* r, uint32_t addr) {
    asm volatile("ldmatrix.sync.aligned.m8n8.x2.shared.b16 {%0,%1}, [%2];"
                 : "=r"(r[0]), "=r"(r[1]) : "r"(addr));
}
__device__ __forceinline__ void mma_bf16(float* c, const uint32_t* a,
                                         const uint32_t* b) {
    asm volatile(
        "mma.sync.aligned.m16n8k16.row.col.f32.bf16.bf16.f32 "
        "{%0,%1,%2,%3}, {%4,%5,%6,%7}, {%8,%9}, {%0,%1,%2,%3};"
        : "+f"(c[0]), "+f"(c[1]), "+f"(c[2]), "+f"(c[3])
        : "r"(a[0]), "r"(a[1]), "r"(a[2]), "r"(a[3]), "r"(b[0]), "r"(b[1]));
}

// ---------------------------------------------------------------------------
// Prep: norms, bf16 conversion (padded), beta = softplus(beta_raw), zero bins.
// ---------------------------------------------------------------------------
__global__ void prep_kernel(const float* __restrict__ x,
                            const float* __restrict__ ex,
                            const float* __restrict__ beta_raw,
                            int B, int NE) {
    const int t = threadIdx.x;
    const int gid = blockIdx.x * 256 + t;
    if (gid < MAXB * NUM_CLASSES) g_class[gid] = 0.f;
    if (gid == 0) {
        float br = beta_raw[0];
        g_beta = (br > 20.f) ? br : log1pf(expf(br));
        g_nsurv = 0u;
    }
    const int R = blockIdx.x * 64 + (t >> 2);   // padded row index
    const int part = t & 3;                      // 16-float segment
    bool is_x = false;
    int outr = R;
    const float* src = nullptr;
    if (R < NE_PAD) {
        if (R < NE) src = ex + (size_t)R * DD + part * 16;
    } else {
        int xr = R - NE_PAD;
        if (xr >= MAXB) return;
        is_x = true; outr = xr;
        if (xr < B) src = x + (size_t)xr * DD + part * 16;
    }
    float v[16];
    float s = 0.f;
    if (src) {
        #pragma unroll
        for (int q = 0; q < 4; q++) {
            float4 f = ((const float4*)src)[q];
            v[4*q+0] = f.x; v[4*q+1] = f.y; v[4*q+2] = f.z; v[4*q+3] = f.w;
            s += f.x*f.x + f.y*f.y + f.z*f.z + f.w*f.w;
        }
    } else {
        #pragma unroll
        for (int q = 0; q < 16; q++) v[q] = 0.f;
    }
    s += __shfl_xor_sync(0xFFFFFFFFu, s, 1);
    s += __shfl_xor_sync(0xFFFFFFFFu, s, 2);
    alignas(16) __nv_bfloat16 hb[16];
    #pragma unroll
    for (int q = 0; q < 16; q++) hb[q] = __float2bfloat16(v[q]);
    __nv_bfloat16* dst =
        (is_x ? (g_xbf + (size_t)outr * DD) : (g_ebf + (size_t)outr * DD)) + part * 16;
    ((uint4*)dst)[0] = ((uint4*)hb)[0];
    ((uint4*)dst)[1] = ((uint4*)hb)[1];
    if (part == 0) {
        if (is_x) g_x2[outr] = (outr < B) ? s : 0.f;
        else      g_e2[outr] = (outr < NE) ? s : 3.0e8f;  // padding: gate never fires
    }
}

// ---------------------------------------------------------------------------
// Main: HMMA filter GEMM. Epilogue is branch-light: a branchless gate builds a
// 64-bit survivor mask; rare survivors are pushed (compacted via smem) into a
// global queue. NO fp32 recompute here — keeps register pressure low so acc
// stays in registers and 2 CTAs/SM fit (one wave).
// ---------------------------------------------------------------------------
__global__ void __launch_bounds__(256, 2)
exemplar_mma_kernel(const int* __restrict__ labels, int B, int NE) {
    __shared__ __align__(16) char sA[TM * ROWB];
    __shared__ __align__(16) char sB[TN * ROWB];
    __shared__ float e2s[TN];
    __shared__ unsigned int s_qbuf[QCAP];
    __shared__ unsigned int s_cnt, s_base;

    const int t = threadIdx.x;
    const int wid = t >> 5, lane = t & 31;
    const int warpM = wid >> 2;            // 0..1
    const int warpN = wid & 3;             // 0..3
    const int bm = blockIdx.y * TM;
    const int NT = (NE + TN - 1) / TN;

    const uint32_t saU = smem_to_u32(sA);
    const uint32_t sbU = smem_to_u32(sB);

    // Load A tile (128 rows x 64 bf16) once.
    for (int i = t; i < TM * 8; i += 256) {
        int r = i >> 3, c = i & 7;
        *(uint4*)(sA + r * ROWB + c * 16) =
            *(const uint4*)(g_xbf + (size_t)(bm + r) * DD + c * 8);
    }

    // ldmatrix lane-address components
    const int rowA = (lane & 7) + ((lane >> 3) & 1) * 8;
    const int kA   = ((lane >> 4) & 1) * 8;
    const int l16  = lane & 15;
    const int rowBf = l16 & 7;
    const int kB    = ((l16 >> 3) & 1) * 8;

    const float beta = g_beta;
    const float thr  = 60.f / beta + 2.f;   // margin 2 >> bf16 dot err (~0.35)

    float x2a[4], x2b[4];
    #pragma unroll
    for (int mi = 0; mi < 4; mi++) {
        int r0 = bm + warpM * 64 + mi * 16 + (lane >> 2);
        x2a[mi] = g_x2[r0];
        x2b[mi] = g_x2[r0 + 8];
    }

    for (int et = blockIdx.x; et < NT; et += GCOLS) {
        const int bn = et * TN;
        __syncthreads();   // prior flush done with sB/e2s/qbuf
        for (int i = t; i < TN * 8; i += 256) {
            int r = i >> 3, c = i & 7;
            *(uint4*)(sB + r * ROWB + c * 16) =
                *(const uint4*)(g_ebf + (size_t)(bn + r) * DD + c * 8);
        }
        for (int i = t; i < TN; i += 256) e2s[i] = g_e2[bn + i];
        if (t == 0) s_cnt = 0u;
        __syncthreads();

        float e2r[4][2];
        #pragma unroll
        for (int ni = 0; ni < 4; ni++) {
            int c0 = warpN * 32 + ni * 8 + 2 * (lane & 3);
            e2r[ni][0] = e2s[c0];
            e2r[ni][1] = e2s[c0 + 1];
        }

        float acc[4][4][4];
        #pragma unroll
        for (int mi = 0; mi < 4; mi++)
            #pragma unroll
            for (int ni = 0; ni < 4; ni++)
                #pragma unroll
                for (int r = 0; r < 4; r++) acc[mi][ni][r] = 0.f;

        #pragma unroll
        for (int ks = 0; ks < 4; ks++) {
            const int k0b = ks * 32;
            uint32_t af[4][4];
            #pragma unroll
            for (int mi = 0; mi < 4; mi++)
                ldsm_x4(af[mi], saU + (uint32_t)(warpM * 64 + mi * 16 + rowA) * ROWB
                                  + kA * 2 + k0b);
            uint32_t bf[4][2];
            #pragma unroll
            for (int ni = 0; ni < 4; ni++)
                ldsm_x2(bf[ni], sbU + (uint32_t)(warpN * 32 + ni * 8 + rowBf) * ROWB
                                  + kB * 2 + k0b);
            #pragma unroll
            for (int mi = 0; mi < 4; mi++)
                #pragma unroll
                for (int ni = 0; ni < 4; ni++)
                    mma_bf16(acc[mi][ni], af[mi], bf[ni]);
        }

        // Branchless gate -> 64-bit survivor mask.
        uint32_t m0 = 0u, m1 = 0u;
        #pragma unroll
        for (int mi = 0; mi < 4; mi++) {
            #pragma unroll
            for (int ni = 0; ni < 4; ni++) {
                #pragma unroll
                for (int r = 0; r < 4; r++) {
                    float x2v = (r >= 2) ? x2b[mi] : x2a[mi];
                    float d2a = x2v + e2r[ni][r & 1] - 2.f * acc[mi][ni][r];
                    uint32_t p = (d2a < thr) ? 1u : 0u;
                    int idx = (mi * 4 + ni) * 4 + r;
                    if (idx < 32) m0 |= p << idx;
                    else          m1 |= p << (idx - 32);
                }
            }
        }

        // Rare slow path: push packed (row,col) survivors into smem queue.
        if (m0 | m1) {
            const int rbase = bm + warpM * 64 + (lane >> 2);
            const int cbase = bn + warpN * 32 + 2 * (lane & 3);
            #pragma unroll
            for (int half = 0; half < 2; half++) {
                uint32_t m = half ? m1 : m0;
                while (m) {
                    int i = __ffs(m) - 1;
                    m &= m - 1;
                    int r  = i & 3;
                    int ni = (i >> 2) & 3;
                    int mi = (i >> 4) + half * 2;
                    int row = rbase + mi * 16 + ((r >> 1) << 3);
                    int col = cbase + ni * 8 + (r & 1);
                    unsigned int q = atomicAdd(&s_cnt, 1u);
                    if (q < QCAP) s_qbuf[q] = ((unsigned)row << 16) | (unsigned)col;
                }
            }
        }
        __syncthreads();
        if (t == 0) {
            unsigned int c = s_cnt;
            if (c > QCAP) c = QCAP;
            s_cnt = c;
            s_base = atomicAdd(&g_nsurv, c);
        }
        __syncthreads();
        for (unsigned int i = t; i < s_cnt; i += 256) {
            unsigned int g = s_base + i;
            if (g < MAXSURV) g_surv[g] = s_qbuf[i];
        }
    }
}

// ---------------------------------------------------------------------------
// Survivors: exact fp32 recompute + exp + scatter-add.
// ---------------------------------------------------------------------------
__global__ void survivor_kernel(const float* __restrict__ x,
                                const float* __restrict__ ex,
                                const int* __restrict__ labels, int B, int NE) {
    unsigned int n = g_nsurv;
    if (n > MAXSURV) n = MAXSURV;
    const float beta = g_beta;
    for (unsigned int i = blockIdx.x * blockDim.x + threadIdx.x; i < n;
         i += gridDim.x * blockDim.x) {
        unsigned int p = g_surv[i];
        int row = (int)(p >> 16);
        int col = (int)(p & 0xFFFFu);
        if (row >= B || col >= NE) continue;
        const float* xr = x  + (size_t)row * DD;
        const float* er = ex + (size_t)col * DD;
        float s = 0.f;
        #pragma unroll
        for (int q = 0; q < DD / 4; q++) {
            float4 a = ((const float4*)xr)[q];
            float4 e = ((const float4*)er)[q];
            s += a.x*e.x + a.y*e.y + a.z*e.z + a.w*e.w;
        }
        float d2 = fmaxf(g_x2[row] + g_e2[col] - 2.f * s, 0.f);
        float bd = beta * d2;
        // skipped mass <= NE*exp(-60) << 1e-3 * EPS
        if (bd < 60.f)
            atomicAdd(&g_class[row * NUM_CLASSES + labels[col]], expf(-bd));
    }
}

// ---------------------------------------------------------------------------
// Finalize: logits = GAMMA * log(class_sims + EPS)
// ---------------------------------------------------------------------------
__global__ void finalize_kernel(float* __restrict__ out, int n) {
    int i = blockIdx.x * blockDim.x + threadIdx.x;
    if (i < n) out[i] = GAMMA * logf(g_class[i] + EPS);
}

// ---------------------------------------------------------------------------
extern "C" void kernel_launch(void* const* d_in, const int* in_sizes, int n_in,
                              void* d_out, int out_size) {
    const float* x        = (const float*)d_in[0];
    const float* ex       = (const float*)d_in[1];
    const int*   labels   = (const int*)d_in[2];
    const float* beta_raw = (const float*)d_in[3];
    float* out = (float*)d_out;

    const int B  = in_sizes[0] / DD;
    const int NE = in_sizes[1] / DD;

    const int prep_blocks = (NE_PAD + MAXB) / 64;   // 798
    prep_kernel<<<prep_blocks, 256>>>(x, ex, beta_raw, B, NE);

    dim3 grid(GCOLS, (B + TM - 1) / TM);            // 37 x 8
    exemplar_mma_kernel<<<grid, 256>>>(labels, B, NE);

    survivor_kernel<<<256, 256>>>(x, ex, labels, B, NE);

    finalize_kernel<<<(out_size + 255) / 256, 256>>>(out, out_size);
}